// round 7
// baseline (speedup 1.0000x reference)
#include <cuda_runtime.h>
#include <cuda_bf16.h>
#include <cstdint>

#define NEG_SLOPE 0.2f
#define STEP (2.0f / 255.0f)
#define AST 132

typedef unsigned long long ull;

__device__ float g_asrc[131072];
__device__ float g_adst[131072];

#define FMA2(d, a, b, c) \
    asm("fma.rn.f32x2 %0, %1, %2, %3;" : "=l"(d) : "l"(a), "l"(b), "l"(c))
#define DUP2(d, s) \
    asm("mov.b64 %0, {%1, %1};" : "=l"(d) : "r"(__float_as_uint(s)))
#define PACK2(d, lo, hi) \
    asm("mov.b64 %0, {%1, %2};" : "=l"(d) : "r"(__float_as_uint(lo)), "r"(__float_as_uint(hi)))
#define UNPACK2(lo, hi, s) do { \
    unsigned _ulo, _uhi; \
    asm("mov.b64 {%0, %1}, %2;" : "=r"(_ulo), "=r"(_uhi) : "l"(s)); \
    lo = __uint_as_float(_ulo); hi = __uint_as_float(_uhi); } while (0)

// ---------------------------------------------------------------------------
// K1: per-node a_src = xg.(W@att_src), a_dst = xg.(W@att_dst)
// ---------------------------------------------------------------------------
__global__ __launch_bounds__(256) void gat_k1(
    const float* __restrict__ x,
    const float* __restrict__ pos_w,
    const float* __restrict__ pos_b,
    const float* __restrict__ lin_w,
    const float* __restrict__ att_src,
    const float* __restrict__ att_dst)
{
    __shared__ float swd[128];
    __shared__ float as_s[64], ad_s[64];
    __shared__ float pw0[64], pw1[64], pb_s[64];
    __shared__ float sc[6];

    const int tid = threadIdx.x;
    const int row = blockIdx.x;
    const int b = row >> 8;
    const int y = row & 255;

    if (tid < 64) {
        as_s[tid] = att_src[tid];
        ad_s[tid] = att_dst[tid];
        pw0[tid]  = pos_w[tid];
        pw1[tid]  = pos_w[64 + tid];
        pb_s[tid] = pos_b[tid];
    }
    __syncthreads();

    if (tid < 64) {
        float s = 0.0f, d = 0.0f;
        const float* lw = lin_w + tid * 64;
        #pragma unroll 8
        for (int co = 0; co < 64; co++) {
            float w = lw[co];
            s = fmaf(w, as_s[co], s);
            d = fmaf(w, ad_s[co], d);
        }
        swd[2 * tid]     = s;
        swd[2 * tid + 1] = d;
    }
    __syncthreads();

    if (tid < 6) {
        const int which = tid % 3;
        const int off   = (tid < 3) ? 0 : 1;
        const float* pv = (which == 0) ? pw0 : (which == 1) ? pw1 : pb_s;
        float acc = 0.0f;
        #pragma unroll 8
        for (int c = 0; c < 64; c++)
            acc = fmaf(pv[c], swd[2 * c + off], acc);
        sc[tid] = acc;
    }
    __syncthreads();

    const float py = -1.0f + (float)y * STEP;
    const float px = -1.0f + (float)tid * STEP;

    ull acc2 = 0ULL;
    const float* xp = x + (((size_t)b << 22) | ((size_t)y << 8)) + tid;
    const ull* wp = (const ull*)swd;
    #pragma unroll 8
    for (int c = 0; c < 64; c++) {
        float v = xp[(size_t)c << 16];
        ull vv; DUP2(vv, v);
        FMA2(acc2, vv, wp[c], acc2);
    }
    float s, d;
    UNPACK2(s, d, acc2);
    s += fmaf(py, sc[0], fmaf(px, sc[1], sc[2]));
    d += fmaf(py, sc[3], fmaf(px, sc[4], sc[5]));

    const int node = (b << 16) + (y << 8) + tid;
    g_asrc[node] = s;
    g_adst[node] = d;
}

// ---------------------------------------------------------------------------
// K2: block = 128 x of one (b,y) row, 256 threads.
//   Phase A (128 thr): alpha[9] + PE sums per x -> SMEM.
//   Phase B: warp w owns channels 8w..8w+7, all 128 x: per (c,row) ONE
//            LDG.128 (4 x) + 2 shuffles + 2 single-lane edge loads; alpha
//            held in 36 regs (9 x LDS.128). z -> zs[k][x] via STS.128.
//   Phase C: block GEMM out = zs.W + bias with fma.rn.f32x2.
// ---------------------------------------------------------------------------
__global__ __launch_bounds__(256) void gat_k2(
    const float* __restrict__ x,
    const float* __restrict__ lin_w,
    const float* __restrict__ pos_w,
    const float* __restrict__ pos_b,
    const float* __restrict__ bias,
    float* __restrict__ out)
{
    __shared__ __align__(16) float zs[64 * 128];    // 32 KB
    __shared__ __align__(16) float wsm[64 * 64];    // 16 KB
    __shared__ __align__(16) float alpha_sh[9 * 128];
    __shared__ float spy_sh[128], spx_sh[128];
    __shared__ float as_sh[3 * AST];
    __shared__ float pw0[64], pw1[64], pb_s[64], b_s[64];

    const int tid  = threadIdx.x;
    const int lane = tid & 31;
    const int wid  = tid >> 5;
    const int blk  = blockIdx.x;       // 1024
    const int b  = blk >> 9;
    const int r  = blk & 511;
    const int y  = r >> 1;
    const int x0 = (r & 1) << 7;

    if (tid < 64) {
        pw0[tid]  = pos_w[tid];
        pw1[tid]  = pos_w[64 + tid];
        pb_s[tid] = pos_b[tid];
        b_s[tid]  = bias[tid];
    }

    // stage W [k][co]
    {
        float4* wp = (float4*)wsm;
        const float4* lw4 = (const float4*)lin_w;
        #pragma unroll
        for (int i = 0; i < 4; i++)
            wp[tid + i * 256] = lw4[tid + i * 256];
    }

    // stage a_src halo
    for (int i = tid; i < 3 * 130; i += 256) {
        int ry = i / 130;
        int xi = i - ry * 130;
        int yy = y - 1 + ry;
        int xg = x0 - 1 + xi;
        float v = -1e30f;
        if ((unsigned)yy < 256u && (unsigned)xg < 256u)
            v = g_asrc[(b << 16) + (yy << 8) + xg];
        as_sh[ry * AST + xi] = v;
    }
    __syncthreads();

    // ---- Phase A: alpha + PE sums (128 threads, one per x) ----
    if (tid < 128) {
        const int xl = tid;
        const int xd = x0 + xl;
        const float ad = g_adst[(b << 16) + (y << 8) + xd];
        float a[9];
        float m = -1e30f;
        #pragma unroll
        for (int ry = 0; ry < 3; ry++) {
            #pragma unroll
            for (int cx = 0; cx < 3; cx++) {
                float e = as_sh[ry * AST + xl + cx] + ad;
                e = (e >= 0.0f) ? e : NEG_SLOPE * e;
                a[ry * 3 + cx] = e;
                m = fmaxf(m, e);
            }
        }
        float ssum = 0.0f;
        #pragma unroll
        for (int j = 0; j < 9; j++) {
            float p = expf(a[j] - m);
            a[j] = p;
            ssum += p;
        }
        const float inv = 1.0f / ssum;
        float sumpy = 0.0f, sumpx = 0.0f;
        #pragma unroll
        for (int j = 0; j < 9; j++) {
            a[j] *= inv;
            alpha_sh[j * 128 + xl] = a[j];
            const float pyv = -1.0f + (float)(y - 1 + j / 3) * STEP;
            const float pxv = -1.0f + (float)(xd - 1 + j % 3) * STEP;
            sumpy = fmaf(a[j], pyv, sumpy);
            sumpx = fmaf(a[j], pxv, sumpx);
        }
        spy_sh[xl] = sumpy;
        spx_sh[xl] = sumpx;
    }
    __syncthreads();

    // ---- Phase B: aggregation, 4 x per thread, 8 channels per warp ----
    {
        float4 A[9];
        #pragma unroll
        for (int j = 0; j < 9; j++)
            A[j] = *(const float4*)&alpha_sh[j * 128 + 4 * lane];
        const float4 SPY = *(const float4*)&spy_sh[4 * lane];
        const float4 SPX = *(const float4*)&spx_sh[4 * lane];

        int ro[3];
        #pragma unroll
        for (int ry = 0; ry < 3; ry++) {
            int yy = y - 1 + ry;
            ro[ry] = (yy < 0 ? 0 : (yy > 255 ? 255 : yy)) << 8;
        }
        const int xlm = (x0 == 0) ? 0 : x0 - 1;
        const int xrm = (x0 + 128 > 255) ? 255 : x0 + 128;
        const int xoff = x0 + 4 * lane;

        const int c0 = wid * 8;
        const float* cbase = x + ((size_t)b << 22) + ((size_t)c0 << 16);

        #pragma unroll 2
        for (int ci = 0; ci < 8; ci++) {
            const int c = c0 + ci;
            const float* cp = cbase + ((size_t)ci << 16);

            float4 z;
            z.x = fmaf(pw0[c], SPY.x, fmaf(pw1[c], SPX.x, pb_s[c]));
            z.y = fmaf(pw0[c], SPY.y, fmaf(pw1[c], SPX.y, pb_s[c]));
            z.z = fmaf(pw0[c], SPY.z, fmaf(pw1[c], SPX.z, pb_s[c]));
            z.w = fmaf(pw0[c], SPY.w, fmaf(pw1[c], SPX.w, pb_s[c]));

            #pragma unroll
            for (int ry = 0; ry < 3; ry++) {
                const float* rp = cp + ro[ry];
                float4 v = *(const float4*)&rp[xoff];
                float l = __shfl_up_sync(0xffffffffu, v.w, 1);
                float rr = __shfl_down_sync(0xffffffffu, v.x, 1);
                if (lane == 0)  l  = rp[xlm];
                if (lane == 31) rr = rp[xrm];
                const float4 a0 = A[ry * 3 + 0];
                const float4 a1 = A[ry * 3 + 1];
                const float4 a2 = A[ry * 3 + 2];
                z.x = fmaf(a0.x, l,   fmaf(a1.x, v.x, fmaf(a2.x, v.y, z.x)));
                z.y = fmaf(a0.y, v.x, fmaf(a1.y, v.y, fmaf(a2.y, v.z, z.y)));
                z.z = fmaf(a0.z, v.y, fmaf(a1.z, v.z, fmaf(a2.z, v.w, z.z)));
                z.w = fmaf(a0.w, v.z, fmaf(a1.w, v.w, fmaf(a2.w, rr,  z.w)));
            }
            *(float4*)&zs[c * 128 + 4 * lane] = z;
        }
    }
    __syncthreads();

    // ---- Phase C: block GEMM (fma.rn.f32x2), thread tile 4x x 8co ----
    const int xq = tid & 31;
    const int cg = tid >> 5;
    const float4* zs4 = (const float4*)zs;
    const ull* w8 = (const ull*)wsm;

    ull acc[4][4];
    {
        ull binit[4];
        #pragma unroll
        for (int p = 0; p < 4; p++)
            PACK2(binit[p], b_s[cg * 8 + 2 * p], b_s[cg * 8 + 2 * p + 1]);
        #pragma unroll
        for (int xi = 0; xi < 4; xi++)
            #pragma unroll
            for (int p = 0; p < 4; p++)
                acc[xi][p] = binit[p];
    }

    #pragma unroll 8
    for (int k = 0; k < 64; k++) {
        const float4 zf = zs4[k * 32 + xq];
        ull z0, z1, z2, z3;
        DUP2(z0, zf.x); DUP2(z1, zf.y); DUP2(z2, zf.z); DUP2(z3, zf.w);
        const longlong2 wA = *(const longlong2*)&w8[k * 32 + cg * 4];
        const longlong2 wB = *(const longlong2*)&w8[k * 32 + cg * 4 + 2];
        const ull w0 = (ull)wA.x, w1 = (ull)wA.y, w2 = (ull)wB.x, w3 = (ull)wB.y;
        FMA2(acc[0][0], z0, w0, acc[0][0]); FMA2(acc[0][1], z0, w1, acc[0][1]);
        FMA2(acc[0][2], z0, w2, acc[0][2]); FMA2(acc[0][3], z0, w3, acc[0][3]);
        FMA2(acc[1][0], z1, w0, acc[1][0]); FMA2(acc[1][1], z1, w1, acc[1][1]);
        FMA2(acc[1][2], z1, w2, acc[1][2]); FMA2(acc[1][3], z1, w3, acc[1][3]);
        FMA2(acc[2][0], z2, w0, acc[2][0]); FMA2(acc[2][1], z2, w1, acc[2][1]);
        FMA2(acc[2][2], z2, w2, acc[2][2]); FMA2(acc[2][3], z2, w3, acc[2][3]);
        FMA2(acc[3][0], z3, w0, acc[3][0]); FMA2(acc[3][1], z3, w1, acc[3][1]);
        FMA2(acc[3][2], z3, w2, acc[3][2]); FMA2(acc[3][3], z3, w3, acc[3][3]);
    }

    {
        float* ob = out + ((size_t)b << 22) + (y << 8) + x0 + xq * 4;
        #pragma unroll
        for (int p = 0; p < 4; p++) {
            const int co = cg * 8 + 2 * p;
            float4 lo4, hi4;
            UNPACK2(lo4.x, hi4.x, acc[0][p]);
            UNPACK2(lo4.y, hi4.y, acc[1][p]);
            UNPACK2(lo4.z, hi4.z, acc[2][p]);
            UNPACK2(lo4.w, hi4.w, acc[3][p]);
            *(float4*)(ob + ((size_t)co << 16))       = lo4;
            *(float4*)(ob + ((size_t)(co + 1) << 16)) = hi4;
        }
    }
}

// ---------------------------------------------------------------------------
extern "C" void kernel_launch(void* const* d_in, const int* in_sizes, int n_in,
                              void* d_out, int out_size)
{
    const float* x       = (const float*)d_in[0];
    const float* pos_w   = (const float*)d_in[1];
    const float* pos_b   = (const float*)d_in[2];
    const float* lin_w   = (const float*)d_in[3];
    const float* att_src = (const float*)d_in[4];
    const float* att_dst = (const float*)d_in[5];
    const float* bias    = (const float*)d_in[6];
    float* out = (float*)d_out;

    gat_k1<<<512, 256>>>(x, pos_w, pos_b, lin_w, att_src, att_dst);
    gat_k2<<<1024, 256>>>(x, lin_w, pos_w, pos_b, bias, out);
}

// round 8
// speedup vs baseline: 1.0216x; 1.0216x over previous
#include <cuda_runtime.h>
#include <cuda_bf16.h>
#include <cstdint>

#define NEG_SLOPE 0.2f
#define STEP (2.0f / 255.0f)

typedef unsigned long long ull;

__device__ float g_asrc[131072];
__device__ float g_adst[131072];

#define FMA2(d, a, b, c) \
    asm("fma.rn.f32x2 %0, %1, %2, %3;" : "=l"(d) : "l"(a), "l"(b), "l"(c))
#define DUP2(d, s) \
    asm("mov.b64 %0, {%1, %1};" : "=l"(d) : "r"(__float_as_uint(s)))
#define PACK2(d, lo, hi) \
    asm("mov.b64 %0, {%1, %2};" : "=l"(d) : "r"(__float_as_uint(lo)), "r"(__float_as_uint(hi)))
#define UNPACK2(lo, hi, s) do { \
    unsigned _ulo, _uhi; \
    asm("mov.b64 {%0, %1}, %2;" : "=r"(_ulo), "=r"(_uhi) : "l"(s)); \
    lo = __uint_as_float(_ulo); hi = __uint_as_float(_uhi); } while (0)

// ---------------------------------------------------------------------------
// K1: per-node a_src = xg.(W@att_src), a_dst = xg.(W@att_dst)
// ---------------------------------------------------------------------------
__global__ __launch_bounds__(256) void gat_k1(
    const float* __restrict__ x,
    const float* __restrict__ pos_w,
    const float* __restrict__ pos_b,
    const float* __restrict__ lin_w,
    const float* __restrict__ att_src,
    const float* __restrict__ att_dst)
{
    __shared__ float swd[128];
    __shared__ float as_s[64], ad_s[64];
    __shared__ float pw0[64], pw1[64], pb_s[64];
    __shared__ float sc[6];

    const int tid = threadIdx.x;
    const int row = blockIdx.x;
    const int b = row >> 8;
    const int y = row & 255;

    if (tid < 64) {
        as_s[tid] = att_src[tid];
        ad_s[tid] = att_dst[tid];
        pw0[tid]  = pos_w[tid];
        pw1[tid]  = pos_w[64 + tid];
        pb_s[tid] = pos_b[tid];
    }
    __syncthreads();

    if (tid < 64) {
        float s = 0.0f, d = 0.0f;
        const float* lw = lin_w + tid * 64;
        #pragma unroll 8
        for (int co = 0; co < 64; co++) {
            float w = lw[co];
            s = fmaf(w, as_s[co], s);
            d = fmaf(w, ad_s[co], d);
        }
        swd[2 * tid]     = s;
        swd[2 * tid + 1] = d;
    }
    __syncthreads();

    if (tid < 6) {
        const int which = tid % 3;
        const int off   = (tid < 3) ? 0 : 1;
        const float* pv = (which == 0) ? pw0 : (which == 1) ? pw1 : pb_s;
        float acc = 0.0f;
        #pragma unroll 8
        for (int c = 0; c < 64; c++)
            acc = fmaf(pv[c], swd[2 * c + off], acc);
        sc[tid] = acc;
    }
    __syncthreads();

    const float py = -1.0f + (float)y * STEP;
    const float px = -1.0f + (float)tid * STEP;

    ull acc2 = 0ULL;
    const float* xp = x + (((size_t)b << 22) | ((size_t)y << 8)) + tid;
    const ull* wp = (const ull*)swd;
    #pragma unroll 8
    for (int c = 0; c < 64; c++) {
        float v = xp[(size_t)c << 16];
        ull vv; DUP2(vv, v);
        FMA2(acc2, vv, wp[c], acc2);
    }
    float s, d;
    UNPACK2(s, d, acc2);
    s += fmaf(py, sc[0], fmaf(px, sc[1], sc[2]));
    d += fmaf(py, sc[3], fmaf(px, sc[4], sc[5]));

    const int node = (b << 16) + (y << 8) + tid;
    g_asrc[node] = s;
    g_adst[node] = d;
}

// ---------------------------------------------------------------------------
// K2: block = 128 x of one (b,y) row, 256 threads, 64-reg budget.
//   Phase A (128 thr): alpha[9] + PE sums per x -> SMEM (a_src via direct LDG).
//   Phase B: warp w owns channels 8w..+7; lane owns 4 x. Per (c,row): one
//            LDG.128 + 2 shuffles + edge loads; alpha taps via LDS.128.
//   Phase C: block GEMM out = zs.W + bias with fma.rn.f32x2.
// ---------------------------------------------------------------------------
__global__ __launch_bounds__(256, 4) void gat_k2(
    const float* __restrict__ x,
    const float* __restrict__ lin_w,
    const float* __restrict__ pos_w,
    const float* __restrict__ pos_b,
    const float* __restrict__ bias,
    float* __restrict__ out)
{
    __shared__ __align__(16) float zs[64 * 128];        // 32 KB
    __shared__ __align__(16) float wsm[64 * 64];        // 16 KB
    __shared__ __align__(16) float alpha_sh[9 * 128];   // 4.5 KB
    __shared__ __align__(16) float spy_sh[128], spx_sh[128];
    __shared__ float pw0[64], pw1[64], pb_s[64], b_s[64];

    const int tid  = threadIdx.x;
    const int lane = tid & 31;
    const int wid  = tid >> 5;
    const int blk  = blockIdx.x;       // 1024
    const int b  = blk >> 9;
    const int r  = blk & 511;
    const int y  = r >> 1;
    const int x0 = (r & 1) << 7;

    if (tid < 64) {
        pw0[tid]  = pos_w[tid];
        pw1[tid]  = pos_w[64 + tid];
        pb_s[tid] = pos_b[tid];
        b_s[tid]  = bias[tid];
    }

    // stage W [k][co]
    {
        float4* wp = (float4*)wsm;
        const float4* lw4 = (const float4*)lin_w;
        #pragma unroll
        for (int i = 0; i < 4; i++)
            wp[tid + i * 256] = lw4[tid + i * 256];
    }

    // ---- Phase A: alpha + PE sums (128 threads, one per x) ----
    if (tid < 128) {
        const int xl = tid;
        const int xd = x0 + xl;
        const float ad = g_adst[(b << 16) + (y << 8) + xd];
        float a[9];
        float m = -1e30f;
        #pragma unroll
        for (int ry = 0; ry < 3; ry++) {
            const int yy = y - 1 + ry;
            const bool rok = (unsigned)yy < 256u;
            #pragma unroll
            for (int cx = 0; cx < 3; cx++) {
                const int xs = xd - 1 + cx;
                float as = -1e30f;
                if (rok && (unsigned)xs < 256u)
                    as = g_asrc[(b << 16) + (yy << 8) + xs];
                float e = as + ad;
                e = (e >= 0.0f) ? e : NEG_SLOPE * e;
                a[ry * 3 + cx] = e;
                m = fmaxf(m, e);
            }
        }
        float ssum = 0.0f;
        #pragma unroll
        for (int j = 0; j < 9; j++) {
            float p = expf(a[j] - m);
            a[j] = p;
            ssum += p;
        }
        const float inv = 1.0f / ssum;
        float sumpy = 0.0f, sumpx = 0.0f;
        #pragma unroll
        for (int j = 0; j < 9; j++) {
            a[j] *= inv;
            alpha_sh[j * 128 + xl] = a[j];
            const float pyv = -1.0f + (float)(y - 1 + j / 3) * STEP;
            const float pxv = -1.0f + (float)(xd - 1 + j % 3) * STEP;
            sumpy = fmaf(a[j], pyv, sumpy);
            sumpx = fmaf(a[j], pxv, sumpx);
        }
        spy_sh[xl] = sumpy;
        spx_sh[xl] = sumpx;
    }
    __syncthreads();

    // ---- Phase B: aggregation, 4 x per thread, 8 channels per warp ----
    {
        const float4 SPY = *(const float4*)&spy_sh[4 * lane];
        const float4 SPX = *(const float4*)&spx_sh[4 * lane];

        int ro[3];
        #pragma unroll
        for (int ry = 0; ry < 3; ry++) {
            int yy = y - 1 + ry;
            ro[ry] = (yy < 0 ? 0 : (yy > 255 ? 255 : yy)) << 8;
        }
        const int xlm = (x0 == 0) ? 0 : x0 - 1;
        const int xrm = (x0 + 128 > 255) ? 255 : x0 + 128;
        const int xoff = x0 + 4 * lane;

        const int c0 = wid * 8;
        const float* cbase = x + ((size_t)b << 22) + ((size_t)c0 << 16);

        #pragma unroll 2
        for (int ci = 0; ci < 8; ci++) {
            const int c = c0 + ci;
            const float* cp = cbase + ((size_t)ci << 16);

            float4 z;
            z.x = fmaf(pw0[c], SPY.x, fmaf(pw1[c], SPX.x, pb_s[c]));
            z.y = fmaf(pw0[c], SPY.y, fmaf(pw1[c], SPX.y, pb_s[c]));
            z.z = fmaf(pw0[c], SPY.z, fmaf(pw1[c], SPX.z, pb_s[c]));
            z.w = fmaf(pw0[c], SPY.w, fmaf(pw1[c], SPX.w, pb_s[c]));

            #pragma unroll
            for (int ry = 0; ry < 3; ry++) {
                const float* rp = cp + ro[ry];
                float4 v = *(const float4*)&rp[xoff];
                float l  = __shfl_up_sync(0xffffffffu, v.w, 1);
                float rr = __shfl_down_sync(0xffffffffu, v.x, 1);
                if (lane == 0)  l  = rp[xlm];
                if (lane == 31) rr = rp[xrm];
                const float4 a0 = *(const float4*)&alpha_sh[(ry * 3 + 0) * 128 + 4 * lane];
                const float4 a1 = *(const float4*)&alpha_sh[(ry * 3 + 1) * 128 + 4 * lane];
                const float4 a2 = *(const float4*)&alpha_sh[(ry * 3 + 2) * 128 + 4 * lane];
                z.x = fmaf(a0.x, l,   fmaf(a1.x, v.x, fmaf(a2.x, v.y, z.x)));
                z.y = fmaf(a0.y, v.x, fmaf(a1.y, v.y, fmaf(a2.y, v.z, z.y)));
                z.z = fmaf(a0.z, v.y, fmaf(a1.z, v.z, fmaf(a2.z, v.w, z.z)));
                z.w = fmaf(a0.w, v.z, fmaf(a1.w, v.w, fmaf(a2.w, rr,  z.w)));
            }
            *(float4*)&zs[c * 128 + 4 * lane] = z;
        }
    }
    __syncthreads();

    // ---- Phase C: block GEMM (fma.rn.f32x2), thread tile 4x x 8co ----
    const int xq = tid & 31;
    const int cg = tid >> 5;
    const float4* zs4 = (const float4*)zs;
    const ull* w8 = (const ull*)wsm;

    ull acc[4][4];
    {
        ull binit[4];
        #pragma unroll
        for (int p = 0; p < 4; p++)
            PACK2(binit[p], b_s[cg * 8 + 2 * p], b_s[cg * 8 + 2 * p + 1]);
        #pragma unroll
        for (int xi = 0; xi < 4; xi++)
            #pragma unroll
            for (int p = 0; p < 4; p++)
                acc[xi][p] = binit[p];
    }

    #pragma unroll 8
    for (int k = 0; k < 64; k++) {
        const float4 zf = zs4[k * 32 + xq];
        ull z0, z1, z2, z3;
        DUP2(z0, zf.x); DUP2(z1, zf.y); DUP2(z2, zf.z); DUP2(z3, zf.w);
        const longlong2 wA = *(const longlong2*)&w8[k * 32 + cg * 4];
        const longlong2 wB = *(const longlong2*)&w8[k * 32 + cg * 4 + 2];
        const ull w0 = (ull)wA.x, w1 = (ull)wA.y, w2 = (ull)wB.x, w3 = (ull)wB.y;
        FMA2(acc[0][0], z0, w0, acc[0][0]); FMA2(acc[0][1], z0, w1, acc[0][1]);
        FMA2(acc[0][2], z0, w2, acc[0][2]); FMA2(acc[0][3], z0, w3, acc[0][3]);
        FMA2(acc[1][0], z1, w0, acc[1][0]); FMA2(acc[1][1], z1, w1, acc[1][1]);
        FMA2(acc[1][2], z1, w2, acc[1][2]); FMA2(acc[1][3], z1, w3, acc[1][3]);
        FMA2(acc[2][0], z2, w0, acc[2][0]); FMA2(acc[2][1], z2, w1, acc[2][1]);
        FMA2(acc[2][2], z2, w2, acc[2][2]); FMA2(acc[2][3], z2, w3, acc[2][3]);
        FMA2(acc[3][0], z3, w0, acc[3][0]); FMA2(acc[3][1], z3, w1, acc[3][1]);
        FMA2(acc[3][2], z3, w2, acc[3][2]); FMA2(acc[3][3], z3, w3, acc[3][3]);
    }

    {
        float* ob = out + ((size_t)b << 22) + (y << 8) + x0 + xq * 4;
        #pragma unroll
        for (int p = 0; p < 4; p++) {
            const int co = cg * 8 + 2 * p;
            float4 lo4, hi4;
            UNPACK2(lo4.x, hi4.x, acc[0][p]);
            UNPACK2(lo4.y, hi4.y, acc[1][p]);
            UNPACK2(lo4.z, hi4.z, acc[2][p]);
            UNPACK2(lo4.w, hi4.w, acc[3][p]);
            *(float4*)(ob + ((size_t)co << 16))       = lo4;
            *(float4*)(ob + ((size_t)(co + 1) << 16)) = hi4;
        }
    }
}

// ---------------------------------------------------------------------------
extern "C" void kernel_launch(void* const* d_in, const int* in_sizes, int n_in,
                              void* d_out, int out_size)
{
    const float* x       = (const float*)d_in[0];
    const float* pos_w   = (const float*)d_in[1];
    const float* pos_b   = (const float*)d_in[2];
    const float* lin_w   = (const float*)d_in[3];
    const float* att_src = (const float*)d_in[4];
    const float* att_dst = (const float*)d_in[5];
    const float* bias    = (const float*)d_in[6];
    float* out = (float*)d_out;

    gat_k1<<<512, 256>>>(x, pos_w, pos_b, lin_w, att_src, att_dst);
    gat_k2<<<1024, 256>>>(x, lin_w, pos_w, pos_b, bias, out);
}

// round 10
// speedup vs baseline: 1.1572x; 1.1328x over previous
#include <cuda_runtime.h>
#include <cuda_bf16.h>
#include <cstdint>

#define NEG_SLOPE 0.2f
#define STEP (2.0f / 255.0f)

typedef unsigned long long ull;

__device__ float g_asrc[131072];
__device__ float g_adst[131072];

#define FMA2(d, a, b, c) \
    asm("fma.rn.f32x2 %0, %1, %2, %3;" : "=l"(d) : "l"(a), "l"(b), "l"(c))
#define DUP2(d, s) \
    asm("mov.b64 %0, {%1, %1};" : "=l"(d) : "r"(__float_as_uint(s)))
#define UNPACK2(lo, hi, s) do { \
    unsigned _ulo, _uhi; \
    asm("mov.b64 {%0, %1}, %2;" : "=r"(_ulo), "=r"(_uhi) : "l"(s)); \
    lo = __uint_as_float(_ulo); hi = __uint_as_float(_uhi); } while (0)

// ---------------------------------------------------------------------------
// K1: per-node a_src = xg.(W@att_src), a_dst = xg.(W@att_dst)   (unchanged)
// ---------------------------------------------------------------------------
__global__ __launch_bounds__(256) void gat_k1(
    const float* __restrict__ x,
    const float* __restrict__ pos_w,
    const float* __restrict__ pos_b,
    const float* __restrict__ lin_w,
    const float* __restrict__ att_src,
    const float* __restrict__ att_dst)
{
    __shared__ float swd[128];
    __shared__ float as_s[64], ad_s[64];
    __shared__ float pw0[64], pw1[64], pb_s[64];
    __shared__ float sc[6];

    const int tid = threadIdx.x;
    const int row = blockIdx.x;
    const int b = row >> 8;
    const int y = row & 255;

    if (tid < 64) {
        as_s[tid] = att_src[tid];
        ad_s[tid] = att_dst[tid];
        pw0[tid]  = pos_w[tid];
        pw1[tid]  = pos_w[64 + tid];
        pb_s[tid] = pos_b[tid];
    }
    __syncthreads();

    if (tid < 64) {
        float s = 0.0f, d = 0.0f;
        const float* lw = lin_w + tid * 64;
        #pragma unroll 8
        for (int co = 0; co < 64; co++) {
            float w = lw[co];
            s = fmaf(w, as_s[co], s);
            d = fmaf(w, ad_s[co], d);
        }
        swd[2 * tid]     = s;
        swd[2 * tid + 1] = d;
    }
    __syncthreads();

    if (tid < 6) {
        const int which = tid % 3;
        const int off   = (tid < 3) ? 0 : 1;
        const float* pv = (which == 0) ? pw0 : (which == 1) ? pw1 : pb_s;
        float acc = 0.0f;
        #pragma unroll 8
        for (int c = 0; c < 64; c++)
            acc = fmaf(pv[c], swd[2 * c + off], acc);
        sc[tid] = acc;
    }
    __syncthreads();

    const float py = -1.0f + (float)y * STEP;
    const float px = -1.0f + (float)tid * STEP;

    ull acc2 = 0ULL;
    const float* xp = x + (((size_t)b << 22) | ((size_t)y << 8)) + tid;
    const ull* wp = (const ull*)swd;
    #pragma unroll 8
    for (int c = 0; c < 64; c++) {
        float v = xp[(size_t)c << 16];
        ull vv; DUP2(vv, v);
        FMA2(acc2, vv, wp[c], acc2);
    }
    float s, d;
    UNPACK2(s, d, acc2);
    s += fmaf(py, sc[0], fmaf(px, sc[1], sc[2]));
    d += fmaf(py, sc[3], fmaf(px, sc[4], sc[5]));

    const int node = (b << 16) + (y << 8) + tid;
    g_asrc[node] = s;
    g_adst[node] = d;
}

// ---------------------------------------------------------------------------
// mma helpers (base PTX, sm_80+ -> valid for sm_103)
// ---------------------------------------------------------------------------
__device__ __forceinline__ uint32_t smem_u32(const void* p) {
    uint32_t r;
    asm("{ .reg .u64 t; cvta.to.shared.u64 t, %1; cvt.u32.u64 %0, t; }"
        : "=r"(r) : "l"(p));
    return r;
}
__device__ __forceinline__ void ldm_x4(uint32_t* r, uint32_t a) {
    asm volatile("ldmatrix.sync.aligned.m8n8.x4.shared.b16 {%0,%1,%2,%3}, [%4];"
        : "=r"(r[0]), "=r"(r[1]), "=r"(r[2]), "=r"(r[3]) : "r"(a));
}
__device__ __forceinline__ void ldm_x4_t(uint32_t* r, uint32_t a) {
    asm volatile("ldmatrix.sync.aligned.m8n8.x4.trans.shared.b16 {%0,%1,%2,%3}, [%4];"
        : "=r"(r[0]), "=r"(r[1]), "=r"(r[2]), "=r"(r[3]) : "r"(a));
}
__device__ __forceinline__ void mma16816(float* c, const uint32_t* a,
                                         uint32_t b0, uint32_t b1) {
    asm volatile(
        "mma.sync.aligned.m16n8k16.row.col.f32.bf16.bf16.f32 "
        "{%0,%1,%2,%3}, {%4,%5,%6,%7}, {%8,%9}, {%0,%1,%2,%3};"
        : "+f"(c[0]), "+f"(c[1]), "+f"(c[2]), "+f"(c[3])
        : "r"(a[0]), "r"(a[1]), "r"(a[2]), "r"(a[3]), "r"(b0), "r"(b1));
}

// tile pitches (bytes)
#define ZPITCH 272   // z tiles [c=64][x=128] bf16, 128 data + 8 pad elems
#define WPITCH 144   // W tiles [co=64][k=64] bf16, 64 data + 8 pad elems

// ---------------------------------------------------------------------------
// K2: block = 128 x of one (b,y) row, 256 threads.
//   Phase A: alpha + PE sums (R8). Phase B: aggregation (R8) + bf16 split of
//   z into k-major tiles zh/zl [c][x]. Phase C: warp-level HMMA GEMM
//   D = Wh.zh + Wh.zl + Wl.zh (fp32), A=W via ldmatrix, B=z via ldmatrix.trans.
//   Epilogue: fragments -> SMEM staging [co][x] (aliases z tiles) -> STG.
// ---------------------------------------------------------------------------
__global__ __launch_bounds__(256, 3) void gat_k2(
    const float* __restrict__ x,
    const float* __restrict__ lin_w,
    const float* __restrict__ pos_w,
    const float* __restrict__ pos_b,
    const float* __restrict__ bias,
    float* __restrict__ out)
{
    __shared__ __align__(16) char tileblob[2 * 64 * ZPITCH];  // zh, zl; later staging
    __shared__ __align__(16) char wblob[2 * 64 * WPITCH];     // Wh, Wl
    __shared__ __align__(16) float alpha_sh[9 * 128];
    __shared__ __align__(16) float spy_sh[128], spx_sh[128];
    __shared__ float pw0[64], pw1[64], pb_s[64], b_s[64];

    const int tid  = threadIdx.x;
    const int lane = tid & 31;
    const int wid  = tid >> 5;
    const int blk  = blockIdx.x;       // 1024
    const int b  = blk >> 9;
    const int r  = blk & 511;
    const int y  = r >> 1;
    const int x0 = (r & 1) << 7;

    char* zh_c = tileblob;
    char* zl_c = tileblob + 64 * ZPITCH;
    char* wh_c = wblob;
    char* wl_c = wblob + 64 * WPITCH;

    if (tid < 64) {
        pw0[tid]  = pos_w[tid];
        pw1[tid]  = pos_w[64 + tid];
        pb_s[tid] = pos_b[tid];
        b_s[tid]  = bias[tid];
    }

    // ---- stage W hi/lo: Wh/Wl[co][k], pitch WPITCH ----
    {
        const int co = tid & 63;
        const int kq = tid >> 6;   // 0..3 -> k = 16kq..+15
        const float* wp = lin_w + co;
        #pragma unroll
        for (int j = 0; j < 8; j++) {
            const int k0 = kq * 16 + 2 * j;
            float w0 = wp[(size_t)k0 * 64];
            float w1 = wp[(size_t)(k0 + 1) * 64];
            __nv_bfloat162 h = __float22bfloat162_rn(make_float2(w0, w1));
            *(uint32_t*)(wh_c + co * WPITCH + k0 * 2) = *(uint32_t*)&h;
            float r0 = w0 - __bfloat162float(h.x);
            float r1 = w1 - __bfloat162float(h.y);
            __nv_bfloat162 l = __float22bfloat162_rn(make_float2(r0, r1));
            *(uint32_t*)(wl_c + co * WPITCH + k0 * 2) = *(uint32_t*)&l;
        }
    }

    // ---- Phase A: alpha + PE sums (128 threads, one per x) ----
    if (tid < 128) {
        const int xl = tid;
        const int xd = x0 + xl;
        const float ad = g_adst[(b << 16) + (y << 8) + xd];
        float a[9];
        float m = -1e30f;
        #pragma unroll
        for (int ry = 0; ry < 3; ry++) {
            const int yy = y - 1 + ry;
            const bool rok = (unsigned)yy < 256u;
            #pragma unroll
            for (int cx = 0; cx < 3; cx++) {
                const int xs = xd - 1 + cx;
                float as = -1e30f;
                if (rok && (unsigned)xs < 256u)
                    as = g_asrc[(b << 16) + (yy << 8) + xs];
                float e = as + ad;
                e = (e >= 0.0f) ? e : NEG_SLOPE * e;
                a[ry * 3 + cx] = e;
                m = fmaxf(m, e);
            }
        }
        float ssum = 0.0f;
        #pragma unroll
        for (int j = 0; j < 9; j++) {
            float p = expf(a[j] - m);
            a[j] = p;
            ssum += p;
        }
        const float inv = 1.0f / ssum;
        float sumpy = 0.0f, sumpx = 0.0f;
        #pragma unroll
        for (int j = 0; j < 9; j++) {
            a[j] *= inv;
            alpha_sh[j * 128 + xl] = a[j];
            const float pyv = -1.0f + (float)(y - 1 + j / 3) * STEP;
            const float pxv = -1.0f + (float)(xd - 1 + j % 3) * STEP;
            sumpy = fmaf(a[j], pyv, sumpy);
            sumpx = fmaf(a[j], pxv, sumpx);
        }
        spy_sh[xl] = sumpy;
        spx_sh[xl] = sumpx;
    }
    __syncthreads();

    // ---- Phase B: aggregation (R8), split z -> zh/zl bf16 [c][x] ----
    {
        const float4 SPY = *(const float4*)&spy_sh[4 * lane];
        const float4 SPX = *(const float4*)&spx_sh[4 * lane];

        int ro[3];
        #pragma unroll
        for (int ry = 0; ry < 3; ry++) {
            int yy = y - 1 + ry;
            ro[ry] = (yy < 0 ? 0 : (yy > 255 ? 255 : yy)) << 8;
        }
        const int xlm = (x0 == 0) ? 0 : x0 - 1;
        const int xrm = (x0 + 128 > 255) ? 255 : x0 + 128;
        const int xoff = x0 + 4 * lane;

        const int c0 = wid * 8;
        const float* cbase = x + ((size_t)b << 22) + ((size_t)c0 << 16);

        #pragma unroll 2
        for (int ci = 0; ci < 8; ci++) {
            const int c = c0 + ci;
            const float* cp = cbase + ((size_t)ci << 16);

            float4 z;
            z.x = fmaf(pw0[c], SPY.x, fmaf(pw1[c], SPX.x, pb_s[c]));
            z.y = fmaf(pw0[c], SPY.y, fmaf(pw1[c], SPX.y, pb_s[c]));
            z.z = fmaf(pw0[c], SPY.z, fmaf(pw1[c], SPX.z, pb_s[c]));
            z.w = fmaf(pw0[c], SPY.w, fmaf(pw1[c], SPX.w, pb_s[c]));

            #pragma unroll
            for (int ry = 0; ry < 3; ry++) {
                const float* rp = cp + ro[ry];
                float4 v = *(const float4*)&rp[xoff];
                float l  = __shfl_up_sync(0xffffffffu, v.w, 1);
                float rr = __shfl_down_sync(0xffffffffu, v.x, 1);
                if (lane == 0)  l  = rp[xlm];
                if (lane == 31) rr = rp[xrm];
                const float4 a0 = *(const float4*)&alpha_sh[(ry * 3 + 0) * 128 + 4 * lane];
                const float4 a1 = *(const float4*)&alpha_sh[(ry * 3 + 1) * 128 + 4 * lane];
                const float4 a2 = *(const float4*)&alpha_sh[(ry * 3 + 2) * 128 + 4 * lane];
                z.x = fmaf(a0.x, l,   fmaf(a1.x, v.x, fmaf(a2.x, v.y, z.x)));
                z.y = fmaf(a0.y, v.x, fmaf(a1.y, v.y, fmaf(a2.y, v.z, z.y)));
                z.z = fmaf(a0.z, v.y, fmaf(a1.z, v.z, fmaf(a2.z, v.w, z.z)));
                z.w = fmaf(a0.w, v.z, fmaf(a1.w, v.w, fmaf(a2.w, rr,  z.w)));
            }

            // split to bf16 hi + residual, store k-major [c][x]
            __nv_bfloat162 h01 = __float22bfloat162_rn(make_float2(z.x, z.y));
            __nv_bfloat162 h23 = __float22bfloat162_rn(make_float2(z.z, z.w));
            float r0 = z.x - __bfloat162float(h01.x);
            float r1 = z.y - __bfloat162float(h01.y);
            float r2 = z.z - __bfloat162float(h23.x);
            float r3 = z.w - __bfloat162float(h23.y);
            __nv_bfloat162 l01 = __float22bfloat162_rn(make_float2(r0, r1));
            __nv_bfloat162 l23 = __float22bfloat162_rn(make_float2(r2, r3));
            uint2 hh; hh.x = *(uint32_t*)&h01; hh.y = *(uint32_t*)&h23;
            uint2 ll; ll.x = *(uint32_t*)&l01; ll.y = *(uint32_t*)&l23;
            *(uint2*)(zh_c + c * ZPITCH + 8 * lane) = hh;
            *(uint2*)(zl_c + c * ZPITCH + 8 * lane) = ll;
        }
    }
    __syncthreads();

    // ---- Phase C: HMMA GEMM. warp: m-tile (co) = (wid&3)*16, x-half = wid>>2 ----
    const int m0 = (wid & 3) << 4;
    const int nb = (wid >> 2) << 6;    // x base 0 or 64

    const uint32_t zh_b = smem_u32(zh_c);
    const uint32_t zl_b = smem_u32(zl_c);
    const uint32_t wh_b = smem_u32(wh_c);
    const uint32_t wl_b = smem_u32(wl_c);

    // per-lane address components
    const uint32_t w_row = (uint32_t)(m0 + (lane & 15)) * WPITCH;
    const uint32_t w_kad = ((lane >> 4) << 3) * 2;
    const uint32_t z_kro = (uint32_t)((lane & 7) + (((lane >> 3) & 1) << 3)) * ZPITCH;
    const uint32_t z_nad = ((lane >> 4) << 3) * 2;

    float acc[8][4];
    #pragma unroll
    for (int i = 0; i < 8; i++)
        #pragma unroll
        for (int j = 0; j < 4; j++) acc[i][j] = 0.0f;

    #pragma unroll
    for (int ks = 0; ks < 4; ks++) {
        const int k0 = ks << 4;
        uint32_t ah[4], al[4];
        ldm_x4(ah, wh_b + w_row + (uint32_t)k0 * 2 + w_kad);
        ldm_x4(al, wl_b + w_row + (uint32_t)k0 * 2 + w_kad);

        #pragma unroll
        for (int np = 0; np < 4; np++) {
            const uint32_t n0 = nb + (np << 4);
            const uint32_t zoff = (uint32_t)k0 * ZPITCH + z_kro + n0 * 2 + z_nad;
            uint32_t bh[4], bl[4];
            ldm_x4_t(bh, zh_b + zoff);
            ldm_x4_t(bl, zl_b + zoff);
            mma16816(acc[2 * np],     ah, bh[0], bh[1]);
            mma16816(acc[2 * np + 1], ah, bh[2], bh[3]);
            mma16816(acc[2 * np],     ah, bl[0], bl[1]);
            mma16816(acc[2 * np + 1], ah, bl[2], bl[3]);
            mma16816(acc[2 * np],     al, bh[0], bh[1]);
            mma16816(acc[2 * np + 1], al, bh[2], bh[3]);
        }
    }
    __syncthreads();   // all ldmatrix reads done; tileblob free for staging

    // ---- epilogue: frags -> staging [co][x] (pitch 132 floats) ----
    float* stage = (float*)tileblob;
    {
        const int co_r = m0 + (lane >> 2);
        #pragma unroll
        for (int nt = 0; nt < 8; nt++) {
            const int xb = nb + nt * 8 + 2 * (lane & 3);
            *(float2*)&stage[co_r * 132 + xb]       = make_float2(acc[nt][0], acc[nt][1]);
            *(float2*)&stage[(co_r + 8) * 132 + xb] = make_float2(acc[nt][2], acc[nt][3]);
        }
    }
    __syncthreads();

    // ---- coalesced copy out + bias ----
    {
        const int xq = lane;          // x = 4*lane..+3
        float* ob = out + ((size_t)b << 22) + (y << 8) + x0 + 4 * xq;
        #pragma unroll
        for (int it = 0; it < 8; it++) {
            const int co = wid + it * 8;
            float4 v = *(const float4*)&stage[co * 132 + 4 * xq];
            const float bv = b_s[co];
            v.x += bv; v.y += bv; v.z += bv; v.w += bv;
            *(float4*)(ob + ((size_t)co << 16)) = v;
        }
    }
}

// ---------------------------------------------------------------------------
extern "C" void kernel_launch(void* const* d_in, const int* in_sizes, int n_in,
                              void* d_out, int out_size)
{
    const float* x       = (const float*)d_in[0];
    const float* pos_w   = (const float*)d_in[1];
    const float* pos_b   = (const float*)d_in[2];
    const float* lin_w   = (const float*)d_in[3];
    const float* att_src = (const float*)d_in[4];
    const float* att_dst = (const float*)d_in[5];
    const float* bias    = (const float*)d_in[6];
    float* out = (float*)d_out;

    gat_k1<<<512, 256>>>(x, pos_w, pos_b, lin_w, att_src, att_dst);
    gat_k2<<<1024, 256>>>(x, lin_w, pos_w, pos_b, bias, out);
}